// round 14
// baseline (speedup 1.0000x reference)
#include <cuda_runtime.h>
#include <cuda_bf16.h>
#include <math.h>
#include <float.h>
#include <stdint.h>

// ---------------------------------------------------------------------------
// DeepRare, persistent kernel (R11 skeleton, best=137us), improved:
//  - 900-float4 units, 2x14.4KB smem buffers -> 5 blocks/SM (occ 60%+)
//  - static unit assignment + syncthreads-free cp.async pipeline in P1/P2
//  - S=240 resize is the identity: direct normalize+threshold
// ---------------------------------------------------------------------------

#define NCH 1472
#define GIDX_TOTAL 28108800
#define NB 740            // 148 SMs x 5 blocks, single wave (GB300 152 ok)
#define NU 8192           // P1/P2 units (<=900 float4 each)
#define SLMAX 900
#define DYNSMEM (2 * SLMAX * 16)

__device__ unsigned g_bar;
__device__ unsigned g_cmin[NCH], g_cmax[NCH];
__device__ unsigned g_hist[NCH][6], g_hist2[NCH][6];
__device__ float g_M[NCH][6], g_Z[NCH];
__device__ __align__(16) unsigned char g_gidx[GIDX_TOTAL];
__device__ __align__(16) float g_proc[306912];
__device__ unsigned g_pmin[5], g_pmax[5];
__device__ float g_resized[5 * 57600];
__device__ unsigned g_rmin[5], g_rmax[5];
__device__ float g_rsum[5];

__device__ __forceinline__ unsigned fenc(float f) {
    unsigned u = __float_as_uint(f);
    return (u & 0x80000000u) ? ~u : (u | 0x80000000u);
}
__device__ __forceinline__ float fdec(unsigned e) {
    return (e & 0x80000000u) ? __uint_as_float(e & 0x7fffffffu)
                             : __uint_as_float(~e);
}

__device__ __forceinline__ void gridbar(unsigned tgt) {
    __syncthreads();
    if (threadIdx.x == 0) {
        __threadfence();
        atomicAdd(&g_bar, 1u);
        volatile unsigned* p = &g_bar;
        while (*p < tgt) { __nanosleep(20); }
        __threadfence();
    }
    __syncthreads();
}

// ---- cp.async primitives ---------------------------------------------------
__device__ __forceinline__ void cp16(uint32_t dst, const void* src) {
    asm volatile("cp.async.cg.shared.global [%0], [%1], 16;\n"
                 :: "r"(dst), "l"(src));
}
__device__ __forceinline__ void cp_commit() {
    asm volatile("cp.async.commit_group;\n");
}
template <int N>
__device__ __forceinline__ void cp_wait() {
    asm volatile("cp.async.wait_group %0;\n" :: "n"(N));
}

__global__ void k_init() {
    int i = blockIdx.x * 256 + threadIdx.x;
    if (i == 0) g_bar = 0u;
    if (i < NCH * 6) {
        ((unsigned*)g_hist)[i] = 0u;
        ((unsigned*)g_hist2)[i] = 0u;
    }
    if (i < NCH) { g_cmin[i] = 0xffffffffu; g_cmax[i] = 0u; }
    if (i < 76512) g_proc[230400 + i] = 0.f;   // l2..l5 (atomic-accumulated)
    if (i < 5) {
        g_pmin[i] = 0xffffffffu; g_pmax[i] = 0u;
        g_rmin[i] = 0xffffffffu; g_rmax[i] = 0u;
        g_rsum[i] = 0.f;
    }
}

// ---- masked float4 (borders -> 0) -------------------------------------------
template <int H, int W>
__device__ __forceinline__ void mask4(int fc, float4 v,
                                      float& v0, float& v1, float& v2, float& v3) {
    if constexpr (W % 4 == 0) {
        constexpr int W4 = W / 4;
        int row = fc / W4;
        int col = fc - row * W4;
        bool br = (row == 0) | (row == H - 1);
        v0 = (br | (col == 0))      ? 0.f : v.x;
        v1 = br                      ? 0.f : v.y;
        v2 = br                      ? 0.f : v.z;
        v3 = (br | (col == W4 - 1)) ? 0.f : v.w;
    } else {
        int e = fc * 4;
        int y0 = e / W, x0 = e - y0 * W;
        int y1 = (e+1) / W, x1 = (e+1) - y1 * W;
        int y2 = (e+2) / W, x2 = (e+2) - y2 * W;
        int y3 = (e+3) / W, x3 = (e+3) - y3 * W;
        v0 = ((y0==0)|(x0==0)|(y0==H-1)|(x0==W-1)) ? 0.f : v.x;
        v1 = ((y1==0)|(x1==0)|(y1==H-1)|(x1==W-1)) ? 0.f : v.y;
        v2 = ((y2==0)|(x2==0)|(y2==H-1)|(x2==W-1)) ? 0.f : v.z;
        v3 = ((y3==0)|(x3==0)|(y3==H-1)|(x3==W-1)) ? 0.f : v.w;
    }
}

// ---- unit geometry (8192 units, <=900 float4) --------------------------------
template <int SL, int CHF4>
__device__ __forceinline__ void issue_unit(const float* __restrict__ in,
                                           int c, int s, uint32_t sbuf) {
    const float4* p4 = (const float4*)in + (size_t)c * CHF4 + (size_t)s * SL;
    constexpr int K = (SL + 255) / 256;
#pragma unroll
    for (int k = 0; k < K; k++) {
        int fl = k * 256 + threadIdx.x;
        if (SL % 256 == 0 || fl < SL) cp16(sbuf + fl * 16, p4 + fl);
    }
}

__device__ __forceinline__ void p12_issue(int u, uint32_t sbuf,
    const float* __restrict__ l1, const float* __restrict__ l2,
    const float* __restrict__ l3, const float* __restrict__ l4,
    const float* __restrict__ l5) {
    if (u < 4096)      issue_unit<900, 57600>(l1, u >> 6, u & 63, sbuf);
    else if (u < 6144) issue_unit<900, 14400>(l2, (u - 4096) >> 4, (u - 4096) & 15, sbuf);
    else if (u < 7168) issue_unit<900, 3600>(l3, (u - 6144) >> 2, (u - 6144) & 3, sbuf);
    else if (u < 7680) issue_unit<900, 900>(l4, u - 7168, 0, sbuf);
    else               issue_unit<225, 225>(l5, u - 7680, 0, sbuf);
}

// -------- P1 process: min/max from smem chunk ----------------------------------
template <int H, int W, int SL>
__device__ __forceinline__ void mm_process(const float4* __restrict__ sbuf,
                                           int choff, int c, int s) {
    const int fbase = s * SL;
    constexpr int K = (SL + 255) / 256;
    float mn = 0.f, mx = 0.f;   // 0 always present in channel (borders)
#pragma unroll
    for (int k = 0; k < K; k++) {
        int fl = k * 256 + threadIdx.x;
        if (SL % 256 == 0 || fl < SL) {
            float4 v = sbuf[fl];
            float v0, v1, v2, v3;
            mask4<H, W>(fbase + fl, v, v0, v1, v2, v3);
            mn = fminf(mn, fminf(fminf(v0, v1), fminf(v2, v3)));
            mx = fmaxf(mx, fmaxf(fmaxf(v0, v1), fmaxf(v2, v3)));
        }
    }
    unsigned emn = __reduce_min_sync(0xffffffffu, fenc(mn));
    unsigned emx = __reduce_max_sync(0xffffffffu, fenc(mx));
    if ((threadIdx.x & 31) == 0) {
        atomicMin(&g_cmin[choff + c], emn);
        atomicMax(&g_cmax[choff + c], emx);
    }
}

__device__ __forceinline__ void p1_process(int u, const float4* sbuf) {
    if (u < 4096)      mm_process<480, 480, 900>(sbuf, 0, u >> 6, u & 63);
    else if (u < 6144) mm_process<240, 240, 900>(sbuf, 64, (u - 4096) >> 4, (u - 4096) & 15);
    else if (u < 7168) mm_process<120, 120, 900>(sbuf, 192, (u - 6144) >> 2, (u - 6144) & 3);
    else if (u < 7680) mm_process<60, 60, 900>(sbuf, 448, u - 7168, 0);
    else               mm_process<30, 30, 225>(sbuf, 960, u - 7680, 0);
}

// -------- P2 process: dual 6-bin hist + gidx from smem chunk --------------------
template <int H, int W, int SL, int CHF4>
__device__ __forceinline__ void hist_process(const float4* __restrict__ sbuf,
                                             int choff, size_t gidxoff,
                                             int c, int s) {
    const int gc = choff + c;
    uchar4* go = (uchar4*)(g_gidx + gidxoff) + (size_t)c * CHF4 + (size_t)s * SL;
    const int fbase = s * SL;
    constexpr int K = (SL + 255) / 256;
    const float mn = fdec(g_cmin[gc]);
    const float mx = fdec(g_cmax[gc]);
    const float rng = mx - mn;
    float inv6, mn6;
    if (rng == 0.f) { inv6 = 0.f; mn6 = 0.f; }
    else { inv6 = __fdiv_rn(1536.f, rng); mn6 = __fmul_rn(-mn, inv6); }
    unsigned pk1 = 0u, pk2 = 0u, nact = 0u;
#pragma unroll
    for (int k = 0; k < K; k++) {
        int fl = k * 256 + threadIdx.x;
        if (SL % 256 == 0 || fl < SL) {
            float4 v = sbuf[fl];
            float vv[4];
            mask4<H, W>(fbase + fl, v, vv[0], vv[1], vv[2], vv[3]);
            unsigned gb[4];
#pragma unroll
            for (int kk = 0; kk < 4; kk++) {
                float u6 = __fmaf_rn(vv[kk], inv6, mn6);
                int iu = (int)floorf(u6);
                int bin = min(5, max(0, iu >> 8));
                int g = min(5, max(0, iu - 1));
                pk1 += 1u << (bin * 6);
                pk2 += 1u << (g * 6);
                gb[kk] = (unsigned)g;
            }
            nact += 4u;
            go[fl] = make_uchar4(gb[0], gb[1], gb[2], gb[3]);
        }
    }
    unsigned f1[6], f2[6], s1 = 0u, s2 = 0u;
#pragma unroll
    for (int b = 0; b < 5; b++) {
        f1[b] = (pk1 >> (b * 6)) & 63u; s1 += f1[b];
        f2[b] = (pk2 >> (b * 6)) & 63u; s2 += f2[b];
    }
    f1[5] = nact - s1; f2[5] = nact - s2;
#pragma unroll
    for (int b = 0; b < 6; b++) {
        f1[b] = __reduce_add_sync(0xffffffffu, f1[b]);
        f2[b] = __reduce_add_sync(0xffffffffu, f2[b]);
    }
    if ((threadIdx.x & 31) == 0) {
#pragma unroll
        for (int b = 0; b < 6; b++) {
            if (f1[b]) atomicAdd(&g_hist[gc][b], f1[b]);
            if (f2[b]) atomicAdd(&g_hist2[gc][b], f2[b]);
        }
    }
}

__device__ __forceinline__ void p2_process(int u, const float4* sbuf) {
    if (u < 4096)      hist_process<480, 480, 900, 57600>(sbuf, 0, 0u, u >> 6, u & 63);
    else if (u < 6144) hist_process<240, 240, 900, 14400>(sbuf, 64, 14745600u, (u - 4096) >> 4, (u - 4096) & 15);
    else if (u < 7168) hist_process<120, 120, 900, 3600>(sbuf, 192, 22118400u, (u - 6144) >> 2, (u - 6144) & 3);
    else if (u < 7680) hist_process<60, 60, 900, 900>(sbuf, 448, 25804800u, u - 7168, 0);
    else               hist_process<30, 30, 225, 225>(sbuf, 960, 27648000u, u - 7680, 0);
}

// -------- P3: closed-form per-channel tables ------------------------------------
__device__ __forceinline__ void stats_ch(int gc) {
    int choff, H, W;
    if (gc < 64)       { choff = 0;   H = 480; W = 480; }
    else if (gc < 192) { choff = 64;  H = 240; W = 240; }
    else if (gc < 448) { choff = 192; H = 120; W = 120; }
    else if (gc < 960) { choff = 448; H = 60;  W = 60;  }
    else               { choff = 960; H = 30;  W = 30;  }
    const int c = gc - choff;
    const float Nf = (float)(H * W);
    const int Nb = 2 * (H + W) - 4;

    float mn = fdec(g_cmin[gc]), mx = fdec(g_cmax[gc]);
    float rng = mx - mn;

    float hl[6]; unsigned h2[6];
#pragma unroll
    for (int b = 0; b < 6; b++) {
        float pr = __fadd_rn(__fdiv_rn((float)g_hist[gc][b], Nf), 1e-4f);
        hl[b] = -logf(pr);
        h2[b] = g_hist2[gc][b];
    }
    float dmin = FLT_MAX, dmax = -FLT_MAX, s = 0.f;
#pragma unroll
    for (int b = 0; b < 6; b++) if (h2[b]) {
        dmin = fminf(dmin, hl[b]); dmax = fmaxf(dmax, hl[b]);
        s += (float)h2[b] * hl[b];
    }
    float drng = dmax - dmin;
    float L[6];
    if (drng == 0.f) {
#pragma unroll
        for (int b = 0; b < 6; b++) L[b] = 0.f;
    } else {
        float meann = (s / Nf - dmin) / drng;
        float t = 1.f - meann;
        float w1 = t * t;
#pragma unroll
        for (int b = 0; b < 6; b++) L[b] = (hl[b] - dmin) / drng * w1;
    }
    // border gidx: EXACTLY the P2 formula applied to v=0 (u6 = mn6)
    int gb = 0;
    if (rng != 0.f) {
        float inv6 = __fdiv_rn(1536.f, rng);
        float mn6 = __fmul_rn(-mn, inv6);
        int iu = (int)floorf(mn6);
        gb = min(5, max(0, iu - 1));
    }
    float mmin = FLT_MAX, mmax = -FLT_MAX, s2 = 0.f;
#pragma unroll
    for (int b = 0; b < 6; b++) {
        unsigned cnt = h2[b];
        if (c > 0 && b == gb) cnt -= (unsigned)Nb;
        if (cnt) {
            mmin = fminf(mmin, L[b]); mmax = fmaxf(mmax, L[b]);
            s2 += (float)cnt * L[b];
        }
    }
    if (c > 0) { mmin = fminf(mmin, 0.f); mmax = fmaxf(mmax, 0.f); }
    float mrng = mmax - mmin;
    if (mrng == 0.f) {
#pragma unroll
        for (int b = 0; b < 6; b++) g_M[gc][b] = 0.f;
        g_Z[gc] = 0.f;
    } else {
        float mmean = s2 / Nf;
        float t = mmax - mmean;
        float w2 = t * t;
#pragma unroll
        for (int b = 0; b < 6; b++) g_M[gc][b] = (L[b] - mmin) / mrng * w2;
        g_Z[gc] = (0.f - mmin) / mrng * w2;
    }
}

// -------- P4 unit: proc += sum of 64 channels of M[c][gidx] ---------------------
template <int C, int H, int W, bool DIRECT>
__device__ __forceinline__ void proc_unit(size_t gidxoff, int procoff,
                                          int choff, int pxblk, int cslice,
                                          float* sM, float* sZ) {
    constexpr int CS = 64;
    constexpr int HW = H * W;
    constexpr int NQ = HW / 4;
    const int cbeg = cslice * CS;
    for (int i = threadIdx.x; i < CS * 6; i += 256)
        sM[i] = ((const float*)g_M)[(choff + cbeg) * 6 + i];
    if (threadIdx.x < CS) sZ[threadIdx.x] = g_Z[choff + cbeg + threadIdx.x];
    __syncthreads();

    int q = pxblk * 256 + threadIdx.x;
    bool act = q < NQ;
    bool bf0 = false, bf1 = false, bf2 = false, bf3 = false;
    if (act) {
        if constexpr (W % 4 == 0) {
            constexpr int W4 = W / 4;
            int row = q / W4, col = q - row * W4;
            bool br = (row == 0) | (row == H - 1);
            bf0 = br | (col == 0); bf1 = br; bf2 = br;
            bf3 = br | (col == W4 - 1);
        } else {
            int e = q * 4;
#pragma unroll
            for (int k = 0; k < 4; k++) {
                int y = (e + k) / W, x = (e + k) - y * W;
                bool bb = (y == 0) | (x == 0) | (y == H - 1) | (x == W - 1);
                if (k == 0) bf0 = bb; else if (k == 1) bf1 = bb;
                else if (k == 2) bf2 = bb; else bf3 = bb;
            }
        }
    }
    bool anyb = __any_sync(0xffffffffu, act && (bf0 | bf1 | bf2 | bf3));
    float a0 = 0.f, a1 = 0.f, a2 = 0.f, a3 = 0.f;
    if (act) {
        const uchar4* gp = (const uchar4*)(g_gidx + gidxoff) + q;
        if (!anyb) {
#pragma unroll 8
            for (int cc = 0; cc < CS; cc++) {
                uchar4 gv = gp[(size_t)(cbeg + cc) * NQ];
                const float* mc = sM + cc * 6;
                a0 += mc[gv.x]; a1 += mc[gv.y]; a2 += mc[gv.z]; a3 += mc[gv.w];
            }
        } else {
#pragma unroll 8
            for (int cc = 0; cc < CS; cc++) {
                uchar4 gv = gp[(size_t)(cbeg + cc) * NQ];
                const float* mc = sM + cc * 6;
                bool ch0 = (cbeg + cc) == 0;   // layer ch 0 keeps border
                float z = sZ[cc];
                a0 += (bf0 && !ch0) ? z : mc[gv.x];
                a1 += (bf1 && !ch0) ? z : mc[gv.y];
                a2 += (bf2 && !ch0) ? z : mc[gv.z];
                a3 += (bf3 && !ch0) ? z : mc[gv.w];
            }
        }
        if constexpr (DIRECT) {
            ((float4*)(g_proc + procoff))[q] = make_float4(a0, a1, a2, a3);
        } else {
            float* pp = g_proc + procoff + q * 4;
            atomicAdd(pp + 0, a0); atomicAdd(pp + 1, a1);
            atomicAdd(pp + 2, a2); atomicAdd(pp + 3, a3);
        }
    }
    __syncthreads();
}

// -------- P6 unit: resize + fused normalize/threshold + r-stats -----------------
template <int S>
__device__ __forceinline__ void resize_unit(int b, int procoff, int layer,
                                            unsigned* sred, float* ssum) {
    int idx = b * 256 + threadIdx.x;   // 57600 = 225*256 exact
    float pmn = fdec(g_pmin[layer]);
    float pmx = fdec(g_pmax[layer]);
    float prng = pmx - pmn;
    float acc;
    if constexpr (S == 240) {
        // identity resize: weights are exactly {1} at yy=oy, xx=ox
        float v = g_proc[procoff + idx];
        float n = (prng == 0.f) ? 0.f : __fdiv_rn(__fsub_rn(v, pmn), prng);
        acc = (n < 0.2f) ? 0.f : n;
    } else {
        int oy = idx / 240, ox = idx - oy * 240;
        constexpr float inv = (float)S / 240.f;
        constexpr float ks = (S > 240) ? inv : 1.f;
        constexpr float iks = 1.f / ks;
        float fy = (oy + 0.5f) * inv - 0.5f;
        float fx = (ox + 0.5f) * inv - 0.5f;
        int y0 = max(0, (int)ceilf(fy - ks)), y1 = min(S - 1, (int)floorf(fy + ks));
        int x0 = max(0, (int)ceilf(fx - ks)), x1 = min(S - 1, (int)floorf(fx + ks));
        float wy[4], wx[4];
        float sy = 0.f, sx = 0.f;
#pragma unroll
        for (int j = 0; j < 4; j++) {
            int yy = y0 + j;
            float w = (yy <= y1) ? fmaxf(0.f, 1.f - fabsf(fy - (float)yy) * iks) : 0.f;
            wy[j] = w; sy += w;
            int xx = x0 + j;
            float v = (xx <= x1) ? fmaxf(0.f, 1.f - fabsf(fx - (float)xx) * iks) : 0.f;
            wx[j] = v; sx += v;
        }
#pragma unroll
        for (int j = 0; j < 4; j++) {
            wy[j] = __fdiv_rn(wy[j], sy);
            wx[j] = __fdiv_rn(wx[j], sx);
        }
        const float* p = g_proc + procoff;
        acc = 0.f;
#pragma unroll
        for (int jy = 0; jy < 4; jy++) {
            if (y0 + jy > y1) break;
            const float* row = p + (y0 + jy) * S;
            float r = 0.f;
#pragma unroll
            for (int jx = 0; jx < 4; jx++) {
                if (x0 + jx > x1) break;
                float v = row[x0 + jx];
                float n = (prng == 0.f) ? 0.f : __fdiv_rn(__fsub_rn(v, pmn), prng);
                n = (n < 0.2f) ? 0.f : n;
                r += wx[jx] * n;
            }
            acc += wy[jy] * r;
        }
    }
    g_resized[layer * 57600 + idx] = acc;

    unsigned* smn = sred; unsigned* smx = sred + 8;
    unsigned emn = __reduce_min_sync(0xffffffffu, fenc(acc));
    unsigned emx = __reduce_max_sync(0xffffffffu, fenc(acc));
    float wsum = acc;
#pragma unroll
    for (int o = 16; o; o >>= 1) wsum += __shfl_xor_sync(0xffffffffu, wsum, o);
    if ((threadIdx.x & 31) == 0) {
        int w = threadIdx.x >> 5;
        smn[w] = emn; smx[w] = emx; ssum[w] = wsum;
    }
    __syncthreads();
    if (threadIdx.x == 0) {
        unsigned a = smn[0], bb = smx[0]; float s = ssum[0];
#pragma unroll
        for (int w = 1; w < 8; w++) {
            a = min(a, smn[w]); bb = max(bb, smx[w]); s += ssum[w];
        }
        atomicMin(&g_rmin[layer], a);
        atomicMax(&g_rmax[layer], bb);
        atomicAdd(&g_rsum[layer], s);
    }
    __syncthreads();
}

__device__ __forceinline__ void p6_dispatch(int u, unsigned* sred, float* ssum) {
    if (u < 225)      resize_unit<480>(u, 0, 0, sred, ssum);
    else if (u < 450) resize_unit<240>(u - 225, 230400, 1, sred, ssum);
    else if (u < 675) resize_unit<120>(u - 450, 288000, 2, sred, ssum);
    else if (u < 900) resize_unit<60>(u - 675, 302400, 3, sred, ssum);
    else              resize_unit<30>(u - 900, 306000, 4, sred, ssum);
}

// ---------------------------- the fused kernel ----------------------------------
__global__ __launch_bounds__(256, 5) void k_main(
    const float* __restrict__ l1, const float* __restrict__ l2,
    const float* __restrict__ l3, const float* __restrict__ l4,
    const float* __restrict__ l5, float* __restrict__ out) {
    extern __shared__ __align__(16) unsigned char dynbuf[];
    const float4* sbp[2] = { (const float4*)dynbuf,
                             (const float4*)(dynbuf + SLMAX * 16) };
    uint32_t sba[2];
    sba[0] = (uint32_t)__cvta_generic_to_shared(dynbuf);
    sba[1] = sba[0] + SLMAX * 16;

    __shared__ float sM[64 * 6];
    __shared__ float sZ[64];
    __shared__ unsigned sred[24];
    __shared__ float ssum[8];
    const int blk = blockIdx.x;

    // ---- P1: minmax, static units, syncthreads-free cp.async pipeline ----
    {
        int cur = blk, pb = 0;
        p12_issue(cur, sba[0], l1, l2, l3, l4, l5);
        cp_commit();
        int nxt = cur + NB;
        bool hn = nxt < NU;
        if (hn) { p12_issue(nxt, sba[1], l1, l2, l3, l4, l5); cp_commit(); }
        while (hn) {
            cp_wait<1>();
            p1_process(cur, sbp[pb]);
            cur = nxt; pb ^= 1;
            nxt = cur + NB; hn = nxt < NU;
            if (hn) { p12_issue(nxt, sba[pb ^ 1], l1, l2, l3, l4, l5); cp_commit(); }
        }
        cp_wait<0>();
        p1_process(cur, sbp[pb]);
    }
    gridbar(1 * NB);

    // ---- P2: hist + gidx, reversed order (recent layers L2-hot) ----
    {
        int k = 0;
        int cur = (NU - 1) - blk, pb = 0;
        p12_issue(cur, sba[0], l1, l2, l3, l4, l5);
        cp_commit();
        int nxt = cur - NB;
        bool hn = nxt >= 0;
        if (hn) { p12_issue(nxt, sba[1], l1, l2, l3, l4, l5); cp_commit(); }
        while (hn) {
            cp_wait<1>();
            p2_process(cur, sbp[pb]);
            cur = nxt; pb ^= 1;
            nxt = cur - NB; hn = nxt >= 0;
            if (hn) { p12_issue(nxt, sba[pb ^ 1], l1, l2, l3, l4, l5); cp_commit(); }
        }
        cp_wait<0>();
        p2_process(cur, sbp[pb]);
        (void)k;
    }
    gridbar(2 * NB);

    // ---- P3: per-channel tables (2 channels per block) ----
    if (threadIdx.x < 2) {
        int gc = blk * 2 + threadIdx.x;
        if (gc < NCH) stats_ch(gc);
    }
    gridbar(3 * NB);

    // ---- P4: proc sums (439 static units) ----
    if (blk < 439) {
        int u = blk;
        if (u < 225)       proc_unit<64, 480, 480, true>(0u, 0, 0, u, 0, sM, sZ);
        else if (u < 339) { int i = u - 225;
                            proc_unit<128, 240, 240, false>(14745600u, 230400, 64, i >> 1, i & 1, sM, sZ); }
        else if (u < 399) { int i = u - 339;
                            proc_unit<256, 120, 120, false>(22118400u, 288000, 192, i >> 2, i & 3, sM, sZ); }
        else if (u < 431) { int i = u - 399;
                            proc_unit<512, 60, 60, false>(25804800u, 302400, 448, i >> 3, i & 7, sM, sZ); }
        else              { int i = u - 431;
                            proc_unit<512, 30, 30, false>(27648000u, 306000, 960, 0, i, sM, sZ); }
    }
    gridbar(4 * NB);

    // ---- P5: all-layer pmin/pmax (76725 float4, 1/thread) ----
    {
        if (threadIdx.x < 5) { sred[threadIdx.x] = 0xffffffffu; sred[12 + threadIdx.x] = 0u; }
        __syncthreads();
        int tg = blk * 256 + threadIdx.x;
        if (tg < 76725) {
            float4 v = ((const float4*)g_proc)[tg];
            int l = (tg < 57600) ? 0 : (tg < 72000) ? 1 : (tg < 75600) ? 2
                  : (tg < 76500) ? 3 : 4;
            float mn = fminf(fminf(v.x, v.y), fminf(v.z, v.w));
            float mx = fmaxf(fmaxf(v.x, v.y), fmaxf(v.z, v.w));
            atomicMin(&sred[l], fenc(mn));
            atomicMax(&sred[12 + l], fenc(mx));
        }
        __syncthreads();
        if (threadIdx.x < 5) {
            atomicMin(&g_pmin[threadIdx.x], sred[threadIdx.x]);
            atomicMax(&g_pmax[threadIdx.x], sred[12 + threadIdx.x]);
        }
    }
    gridbar(5 * NB);

    // ---- P6: resize (1125 static units, 2 rounds) ----
    p6_dispatch(blk, sred, ssum);
    if (blk + NB < 1125) p6_dispatch(blk + NB, sred, ssum);
    gridbar(6 * NB);

    // ---- P7: final groups + sum ----
    if (blk < 225) {
        int idx = blk * 256 + threadIdx.x;
        float s = 0.f;
#pragma unroll
        for (int l = 0; l < 5; l++) {
            float v = g_resized[l * 57600 + idx];
            float rmn = fdec(g_rmin[l]);
            float rmx = fdec(g_rmax[l]);
            float rrng = rmx - rmn;
            float rmean = g_rsum[l] / 57600.f;
            float t = rmx - rmean;
            float w3 = t * t;
            float g = (rrng == 0.f || w3 == 0.f)
                      ? 0.f
                      : __fmul_rn(__fdiv_rn(__fsub_rn(v, rmn), rrng), 256.f);
            s += g;
            out[57600 + idx * 5 + l] = g;
        }
        out[idx] = s;
    }
}

extern "C" void kernel_launch(void* const* d_in, const int* in_sizes, int n_in,
                              void* d_out, int out_size) {
    const float* l1 = (const float*)d_in[0];
    const float* l2 = (const float*)d_in[1];
    const float* l3 = (const float*)d_in[2];
    const float* l4 = (const float*)d_in[3];
    const float* l5 = (const float*)d_in[4];
    float* out = (float*)d_out;

    cudaFuncSetAttribute(k_main, cudaFuncAttributeMaxDynamicSharedMemorySize,
                         DYNSMEM);
    k_init<<<300, 256>>>();
    k_main<<<NB, 256, DYNSMEM>>>(l1, l2, l3, l4, l5, out);
}

// round 15
// speedup vs baseline: 1.0649x; 1.0649x over previous
#include <cuda_runtime.h>
#include <cuda_bf16.h>
#include <math.h>
#include <float.h>
#include <stdint.h>

// ---------------------------------------------------------------------------
// DeepRare, persistent kernel (R11 champion skeleton) with:
//  - P1/P2 fused via per-channel arrival counters (no global barrier; the two
//    113MB passes overlap)
//  - P3 stats computed inline by the last hist-arriver per channel
//  - S=240 resize replaced by its algebraic identity
// ---------------------------------------------------------------------------

#define NCH 1472
#define GIDX_TOTAL 28108800
#define NB 444            // 148 SMs x 3 blocks, single wave (GB300 152 ok)
#define SLMAX 1800        // max unit size in float4 (28.8 KB)
#define DYNSMEM (2 * SLMAX * 16)

__device__ unsigned g_bar;
__device__ unsigned g_ctr[4];
__device__ unsigned g_arr1[NCH], g_arr2[NCH];
__device__ unsigned g_cmin[NCH], g_cmax[NCH];
__device__ unsigned g_hist[NCH][6], g_hist2[NCH][6];
__device__ float g_M[NCH][6], g_Z[NCH];
__device__ __align__(16) unsigned char g_gidx[GIDX_TOTAL];
__device__ __align__(16) float g_proc[306912];
__device__ unsigned g_pmin[5], g_pmax[5];
__device__ float g_resized[5 * 57600];
__device__ unsigned g_rmin[5], g_rmax[5];
__device__ float g_rsum[5];

__device__ __forceinline__ unsigned fenc(float f) {
    unsigned u = __float_as_uint(f);
    return (u & 0x80000000u) ? ~u : (u | 0x80000000u);
}
__device__ __forceinline__ float fdec(unsigned e) {
    return (e & 0x80000000u) ? __uint_as_float(e & 0x7fffffffu)
                             : __uint_as_float(~e);
}

__device__ __forceinline__ void gridbar(unsigned tgt) {
    __syncthreads();
    if (threadIdx.x == 0) {
        __threadfence();
        atomicAdd(&g_bar, 1u);
        volatile unsigned* p = &g_bar;
        while (*p < tgt) { __nanosleep(20); }
        __threadfence();
    }
    __syncthreads();
}

// ---- cp.async primitives ---------------------------------------------------
__device__ __forceinline__ void cp16(uint32_t dst, const void* src) {
    asm volatile("cp.async.cg.shared.global [%0], [%1], 16;\n"
                 :: "r"(dst), "l"(src));
}
__device__ __forceinline__ void cp_commit() {
    asm volatile("cp.async.commit_group;\n");
}
template <int N>
__device__ __forceinline__ void cp_wait() {
    asm volatile("cp.async.wait_group %0;\n" :: "n"(N));
}

__global__ void k_init() {
    int i = blockIdx.x * 256 + threadIdx.x;
    if (i == 0) g_bar = 0u;
    if (i < 4) g_ctr[i] = 0u;
    if (i < NCH) { g_arr1[i] = 0u; g_arr2[i] = 0u; }
    if (i < NCH * 6) {
        ((unsigned*)g_hist)[i] = 0u;
        ((unsigned*)g_hist2)[i] = 0u;
    }
    if (i < NCH) { g_cmin[i] = 0xffffffffu; g_cmax[i] = 0u; }
    if (i < 76512) g_proc[230400 + i] = 0.f;   // l2..l5 (atomic-accumulated)
    if (i < 5) {
        g_pmin[i] = 0xffffffffu; g_pmax[i] = 0u;
        g_rmin[i] = 0xffffffffu; g_rmax[i] = 0u;
        g_rsum[i] = 0.f;
    }
}

// ---- masked float4 (borders -> 0) -------------------------------------------
template <int H, int W>
__device__ __forceinline__ void mask4(int fc, float4 v,
                                      float& v0, float& v1, float& v2, float& v3) {
    if constexpr (W % 4 == 0) {
        constexpr int W4 = W / 4;
        int row = fc / W4;
        int col = fc - row * W4;
        bool br = (row == 0) | (row == H - 1);
        v0 = (br | (col == 0))      ? 0.f : v.x;
        v1 = br                      ? 0.f : v.y;
        v2 = br                      ? 0.f : v.z;
        v3 = (br | (col == W4 - 1)) ? 0.f : v.w;
    } else {
        int e = fc * 4;
        int y0 = e / W, x0 = e - y0 * W;
        int y1 = (e+1) / W, x1 = (e+1) - y1 * W;
        int y2 = (e+2) / W, x2 = (e+2) - y2 * W;
        int y3 = (e+3) / W, x3 = (e+3) - y3 * W;
        v0 = ((y0==0)|(x0==0)|(y0==H-1)|(x0==W-1)) ? 0.f : v.x;
        v1 = ((y1==0)|(x1==0)|(y1==H-1)|(x1==W-1)) ? 0.f : v.y;
        v2 = ((y2==0)|(x2==0)|(y2==H-1)|(x2==W-1)) ? 0.f : v.z;
        v3 = ((y3==0)|(x3==0)|(y3==H-1)|(x3==W-1)) ? 0.f : v.w;
    }
}

// ---- unit geometry (4608 units; chunks/channel: l1=32 l2=8 l3=2 l4=1 l5=1) ---
template <int SL, int CHF4>
__device__ __forceinline__ void issue_unit(const float* __restrict__ in,
                                           int c, int s, uint32_t sbuf) {
    const float4* p4 = (const float4*)in + (size_t)c * CHF4 + (size_t)s * SL;
    constexpr int K = (SL + 255) / 256;
#pragma unroll
    for (int k = 0; k < K; k++) {
        int fl = k * 256 + threadIdx.x;
        if (SL % 256 == 0 || fl < SL) cp16(sbuf + fl * 16, p4 + fl);
    }
}

__device__ __forceinline__ void p12_issue(int u, uint32_t sbuf,
    const float* __restrict__ l1, const float* __restrict__ l2,
    const float* __restrict__ l3, const float* __restrict__ l4,
    const float* __restrict__ l5) {
    if (u < 2048)      issue_unit<1800, 57600>(l1, u >> 5, u & 31, sbuf);
    else if (u < 3072) issue_unit<1800, 14400>(l2, (u - 2048) >> 3, (u - 2048) & 7, sbuf);
    else if (u < 3584) issue_unit<1800, 3600>(l3, (u - 3072) >> 1, (u - 3072) & 1, sbuf);
    else if (u < 4096) issue_unit<900, 900>(l4, u - 3584, 0, sbuf);
    else               issue_unit<225, 225>(l5, u - 4096, 0, sbuf);
}

// -------- P1 process: min/max from smem chunk + release arrival ---------------
template <int H, int W, int SL>
__device__ __forceinline__ void mm_process(const float4* __restrict__ sbuf,
                                           int choff, int c, int s) {
    const int gc = choff + c;
    const int fbase = s * SL;
    constexpr int K = (SL + 255) / 256;
    float mn = 0.f, mx = 0.f;   // 0 always present in channel (borders)
#pragma unroll
    for (int k = 0; k < K; k++) {
        int fl = k * 256 + threadIdx.x;
        if (SL % 256 == 0 || fl < SL) {
            float4 v = sbuf[fl];
            float v0, v1, v2, v3;
            mask4<H, W>(fbase + fl, v, v0, v1, v2, v3);
            mn = fminf(mn, fminf(fminf(v0, v1), fminf(v2, v3)));
            mx = fmaxf(mx, fmaxf(fmaxf(v0, v1), fmaxf(v2, v3)));
        }
    }
    unsigned emn = __reduce_min_sync(0xffffffffu, fenc(mn));
    unsigned emx = __reduce_max_sync(0xffffffffu, fenc(mx));
    if ((threadIdx.x & 31) == 0) {
        atomicMin(&g_cmin[gc], emn);
        atomicMax(&g_cmax[gc], emx);
        __threadfence();
        atomicAdd(&g_arr1[gc], 1u);   // warp-level arrival (release)
    }
}

__device__ __forceinline__ void p1_process(int u, const float4* sbuf) {
    if (u < 2048)      mm_process<480, 480, 1800>(sbuf, 0, u >> 5, u & 31);
    else if (u < 3072) mm_process<240, 240, 1800>(sbuf, 64, (u - 2048) >> 3, (u - 2048) & 7);
    else if (u < 3584) mm_process<120, 120, 1800>(sbuf, 192, (u - 3072) >> 1, (u - 3072) & 1);
    else if (u < 4096) mm_process<60, 60, 900>(sbuf, 448, u - 3584, 0);
    else               mm_process<30, 30, 225>(sbuf, 960, u - 4096, 0);
}

// -------- P3 stats (inline, run by last hist arriver of a channel) ------------
__device__ void stats_ch(int gc) {
    int choff, H, W;
    if (gc < 64)       { choff = 0;   H = 480; W = 480; }
    else if (gc < 192) { choff = 64;  H = 240; W = 240; }
    else if (gc < 448) { choff = 192; H = 120; W = 120; }
    else if (gc < 960) { choff = 448; H = 60;  W = 60;  }
    else               { choff = 960; H = 30;  W = 30;  }
    const int c = gc - choff;
    const float Nf = (float)(H * W);
    const int Nb = 2 * (H + W) - 4;

    float mn = fdec(g_cmin[gc]), mx = fdec(g_cmax[gc]);
    float rng = mx - mn;

    float hl[6]; unsigned h2[6];
#pragma unroll
    for (int b = 0; b < 6; b++) {
        float pr = __fadd_rn(__fdiv_rn((float)g_hist[gc][b], Nf), 1e-4f);
        hl[b] = -logf(pr);
        h2[b] = g_hist2[gc][b];
    }
    float dmin = FLT_MAX, dmax = -FLT_MAX, s = 0.f;
#pragma unroll
    for (int b = 0; b < 6; b++) if (h2[b]) {
        dmin = fminf(dmin, hl[b]); dmax = fmaxf(dmax, hl[b]);
        s += (float)h2[b] * hl[b];
    }
    float drng = dmax - dmin;
    float L[6];
    if (drng == 0.f) {
#pragma unroll
        for (int b = 0; b < 6; b++) L[b] = 0.f;
    } else {
        float meann = (s / Nf - dmin) / drng;
        float t = 1.f - meann;
        float w1 = t * t;
#pragma unroll
        for (int b = 0; b < 6; b++) L[b] = (hl[b] - dmin) / drng * w1;
    }
    // border gidx: EXACTLY the P2 formula applied to v=0 (u6 = mn6)
    int gb = 0;
    if (rng != 0.f) {
        float inv6 = __fdiv_rn(1536.f, rng);
        float mn6 = __fmul_rn(-mn, inv6);
        int iu = (int)floorf(mn6);
        gb = min(5, max(0, iu - 1));
    }
    float mmin = FLT_MAX, mmax = -FLT_MAX, s2 = 0.f;
#pragma unroll
    for (int b = 0; b < 6; b++) {
        unsigned cnt = h2[b];
        if (c > 0 && b == gb) cnt -= (unsigned)Nb;
        if (cnt) {
            mmin = fminf(mmin, L[b]); mmax = fmaxf(mmax, L[b]);
            s2 += (float)cnt * L[b];
        }
    }
    if (c > 0) { mmin = fminf(mmin, 0.f); mmax = fmaxf(mmax, 0.f); }
    float mrng = mmax - mmin;
    if (mrng == 0.f) {
#pragma unroll
        for (int b = 0; b < 6; b++) g_M[gc][b] = 0.f;
        g_Z[gc] = 0.f;
    } else {
        float mmean = s2 / Nf;
        float t = mmax - mmean;
        float w2 = t * t;
#pragma unroll
        for (int b = 0; b < 6; b++) g_M[gc][b] = (L[b] - mmin) / mrng * w2;
        g_Z[gc] = (0.f - mmin) / mrng * w2;
    }
    __threadfence();
}

// -------- P2 process: acquire channel min/max, hist+gidx, inline stats ---------
template <int H, int W, int SL, int CHF4, int TGT>
__device__ __forceinline__ void hist_process(const float4* __restrict__ sbuf,
                                             int choff, size_t gidxoff,
                                             int c, int s) {
    const int gc = choff + c;
    // acquire: wait for all TGT warp-arrivals of this channel's minmax
    float mn, mx;
    {
        float m0 = 0.f, m1 = 0.f;
        if ((threadIdx.x & 31) == 0) {
            volatile unsigned* pa = &g_arr1[gc];
            while (*pa < (unsigned)TGT) { __nanosleep(20); }
            __threadfence();
            m0 = fdec(g_cmin[gc]);
            m1 = fdec(g_cmax[gc]);
        }
        mn = __shfl_sync(0xffffffffu, m0, 0);
        mx = __shfl_sync(0xffffffffu, m1, 0);
    }
    uchar4* go = (uchar4*)(g_gidx + gidxoff) + (size_t)c * CHF4 + (size_t)s * SL;
    const int fbase = s * SL;
    constexpr int K = (SL + 255) / 256;
    const float rng = mx - mn;
    float inv6, mn6;
    if (rng == 0.f) { inv6 = 0.f; mn6 = 0.f; }
    else { inv6 = __fdiv_rn(1536.f, rng); mn6 = __fmul_rn(-mn, inv6); }
    unsigned pk1 = 0u, pk2 = 0u, nact = 0u;
#pragma unroll
    for (int k = 0; k < K; k++) {
        int fl = k * 256 + threadIdx.x;
        if (SL % 256 == 0 || fl < SL) {
            float4 v = sbuf[fl];
            float vv[4];
            mask4<H, W>(fbase + fl, v, vv[0], vv[1], vv[2], vv[3]);
            unsigned gb[4];
#pragma unroll
            for (int kk = 0; kk < 4; kk++) {
                float u6 = __fmaf_rn(vv[kk], inv6, mn6);
                int iu = (int)floorf(u6);
                int bin = min(5, max(0, iu >> 8));
                int g = min(5, max(0, iu - 1));
                pk1 += 1u << (bin * 6);
                pk2 += 1u << (g * 6);
                gb[kk] = (unsigned)g;
            }
            nact += 4u;
            go[fl] = make_uchar4(gb[0], gb[1], gb[2], gb[3]);
        }
    }
    unsigned f1[6], f2[6], s1 = 0u, s2 = 0u;
#pragma unroll
    for (int b = 0; b < 5; b++) {
        f1[b] = (pk1 >> (b * 6)) & 63u; s1 += f1[b];
        f2[b] = (pk2 >> (b * 6)) & 63u; s2 += f2[b];
    }
    f1[5] = nact - s1; f2[5] = nact - s2;
#pragma unroll
    for (int b = 0; b < 6; b++) {
        f1[b] = __reduce_add_sync(0xffffffffu, f1[b]);
        f2[b] = __reduce_add_sync(0xffffffffu, f2[b]);
    }
    if ((threadIdx.x & 31) == 0) {
#pragma unroll
        for (int b = 0; b < 6; b++) {
            if (f1[b]) atomicAdd(&g_hist[gc][b], f1[b]);
            if (f2[b]) atomicAdd(&g_hist2[gc][b], f2[b]);
        }
        __threadfence();
        unsigned old = atomicAdd(&g_arr2[gc], 1u);
        if (old == (unsigned)(TGT - 1)) stats_ch(gc);   // last arriver folds P3
    }
}

__device__ __forceinline__ void p2_process(int u, const float4* sbuf) {
    if (u < 2048)      hist_process<480, 480, 1800, 57600, 256>(sbuf, 0, 0u, u >> 5, u & 31);
    else if (u < 3072) hist_process<240, 240, 1800, 14400, 64>(sbuf, 64, 14745600u, (u - 2048) >> 3, (u - 2048) & 7);
    else if (u < 3584) hist_process<120, 120, 1800, 3600, 16>(sbuf, 192, 22118400u, (u - 3072) >> 1, (u - 3072) & 1);
    else if (u < 4096) hist_process<60, 60, 900, 900, 8>(sbuf, 448, 25804800u, u - 3584, 0);
    else               hist_process<30, 30, 225, 225, 8>(sbuf, 960, 27648000u, u - 4096, 0);
}

// -------- P4 unit: proc += sum of 64 channels of M[c][gidx] -------------------
template <int C, int H, int W, bool DIRECT>
__device__ __forceinline__ void proc_unit(size_t gidxoff, int procoff,
                                          int choff, int pxblk, int cslice,
                                          float* sM, float* sZ) {
    constexpr int CS = 64;
    constexpr int HW = H * W;
    constexpr int NQ = HW / 4;
    const int cbeg = cslice * CS;
    for (int i = threadIdx.x; i < CS * 6; i += 256)
        sM[i] = ((const float*)g_M)[(choff + cbeg) * 6 + i];
    if (threadIdx.x < CS) sZ[threadIdx.x] = g_Z[choff + cbeg + threadIdx.x];
    __syncthreads();

    int q = pxblk * 256 + threadIdx.x;
    bool act = q < NQ;
    bool bf0 = false, bf1 = false, bf2 = false, bf3 = false;
    if (act) {
        if constexpr (W % 4 == 0) {
            constexpr int W4 = W / 4;
            int row = q / W4, col = q - row * W4;
            bool br = (row == 0) | (row == H - 1);
            bf0 = br | (col == 0); bf1 = br; bf2 = br;
            bf3 = br | (col == W4 - 1);
        } else {
            int e = q * 4;
#pragma unroll
            for (int k = 0; k < 4; k++) {
                int y = (e + k) / W, x = (e + k) - y * W;
                bool bb = (y == 0) | (x == 0) | (y == H - 1) | (x == W - 1);
                if (k == 0) bf0 = bb; else if (k == 1) bf1 = bb;
                else if (k == 2) bf2 = bb; else bf3 = bb;
            }
        }
    }
    bool anyb = __any_sync(0xffffffffu, act && (bf0 | bf1 | bf2 | bf3));
    float a0 = 0.f, a1 = 0.f, a2 = 0.f, a3 = 0.f;
    if (act) {
        const uchar4* gp = (const uchar4*)(g_gidx + gidxoff) + q;
        if (!anyb) {
#pragma unroll 8
            for (int cc = 0; cc < CS; cc++) {
                uchar4 gv = gp[(size_t)(cbeg + cc) * NQ];
                const float* mc = sM + cc * 6;
                a0 += mc[gv.x]; a1 += mc[gv.y]; a2 += mc[gv.z]; a3 += mc[gv.w];
            }
        } else {
#pragma unroll 8
            for (int cc = 0; cc < CS; cc++) {
                uchar4 gv = gp[(size_t)(cbeg + cc) * NQ];
                const float* mc = sM + cc * 6;
                bool ch0 = (cbeg + cc) == 0;   // layer ch 0 keeps border
                float z = sZ[cc];
                a0 += (bf0 && !ch0) ? z : mc[gv.x];
                a1 += (bf1 && !ch0) ? z : mc[gv.y];
                a2 += (bf2 && !ch0) ? z : mc[gv.z];
                a3 += (bf3 && !ch0) ? z : mc[gv.w];
            }
        }
        if constexpr (DIRECT) {
            ((float4*)(g_proc + procoff))[q] = make_float4(a0, a1, a2, a3);
        } else {
            float* pp = g_proc + procoff + q * 4;
            atomicAdd(pp + 0, a0); atomicAdd(pp + 1, a1);
            atomicAdd(pp + 2, a2); atomicAdd(pp + 3, a3);
        }
    }
    __syncthreads();
}

// -------- P6 unit: resize + fused normalize/threshold + r-stats ---------------
template <int S>
__device__ __forceinline__ void resize_unit(int b, int procoff, int layer,
                                            unsigned* sred, float* ssum) {
    int idx = b * 256 + threadIdx.x;   // 57600 = 225*256 exact
    float pmn = fdec(g_pmin[layer]);
    float pmx = fdec(g_pmax[layer]);
    float prng = pmx - pmn;
    float acc;
    if constexpr (S == 240) {
        // identity: triangle weights are exactly {0,1,0} at scale 1
        float v = g_proc[procoff + idx];
        float n = (prng == 0.f) ? 0.f : __fdiv_rn(__fsub_rn(v, pmn), prng);
        acc = (n < 0.2f) ? 0.f : n;
    } else {
        int oy = idx / 240, ox = idx - oy * 240;
        constexpr float inv = (float)S / 240.f;
        constexpr float ks = (S > 240) ? inv : 1.f;
        constexpr float iks = 1.f / ks;
        float fy = (oy + 0.5f) * inv - 0.5f;
        float fx = (ox + 0.5f) * inv - 0.5f;
        int y0 = max(0, (int)ceilf(fy - ks)), y1 = min(S - 1, (int)floorf(fy + ks));
        int x0 = max(0, (int)ceilf(fx - ks)), x1 = min(S - 1, (int)floorf(fx + ks));
        float wy[4], wx[4];
        float sy = 0.f, sx = 0.f;
#pragma unroll
        for (int j = 0; j < 4; j++) {
            int yy = y0 + j;
            float w = (yy <= y1) ? fmaxf(0.f, 1.f - fabsf(fy - (float)yy) * iks) : 0.f;
            wy[j] = w; sy += w;
            int xx = x0 + j;
            float v = (xx <= x1) ? fmaxf(0.f, 1.f - fabsf(fx - (float)xx) * iks) : 0.f;
            wx[j] = v; sx += v;
        }
#pragma unroll
        for (int j = 0; j < 4; j++) {
            wy[j] = __fdiv_rn(wy[j], sy);
            wx[j] = __fdiv_rn(wx[j], sx);
        }
        const float* p = g_proc + procoff;
        acc = 0.f;
#pragma unroll
        for (int jy = 0; jy < 4; jy++) {
            if (y0 + jy > y1) break;
            const float* row = p + (y0 + jy) * S;
            float r = 0.f;
#pragma unroll
            for (int jx = 0; jx < 4; jx++) {
                if (x0 + jx > x1) break;
                float v = row[x0 + jx];
                float n = (prng == 0.f) ? 0.f : __fdiv_rn(__fsub_rn(v, pmn), prng);
                n = (n < 0.2f) ? 0.f : n;
                r += wx[jx] * n;
            }
            acc += wy[jy] * r;
        }
    }
    g_resized[layer * 57600 + idx] = acc;

    unsigned* smn = sred; unsigned* smx = sred + 8;
    unsigned emn = __reduce_min_sync(0xffffffffu, fenc(acc));
    unsigned emx = __reduce_max_sync(0xffffffffu, fenc(acc));
    float wsum = acc;
#pragma unroll
    for (int o = 16; o; o >>= 1) wsum += __shfl_xor_sync(0xffffffffu, wsum, o);
    if ((threadIdx.x & 31) == 0) {
        int w = threadIdx.x >> 5;
        smn[w] = emn; smx[w] = emx; ssum[w] = wsum;
    }
    __syncthreads();
    if (threadIdx.x == 0) {
        unsigned a = smn[0], bb = smx[0]; float s = ssum[0];
#pragma unroll
        for (int w = 1; w < 8; w++) {
            a = min(a, smn[w]); bb = max(bb, smx[w]); s += ssum[w];
        }
        atomicMin(&g_rmin[layer], a);
        atomicMax(&g_rmax[layer], bb);
        atomicAdd(&g_rsum[layer], s);
    }
    __syncthreads();
}

// ---------------------------- the fused kernel --------------------------------
__global__ __launch_bounds__(256, 3) void k_main(
    const float* __restrict__ l1, const float* __restrict__ l2,
    const float* __restrict__ l3, const float* __restrict__ l4,
    const float* __restrict__ l5, float* __restrict__ out) {
    extern __shared__ __align__(16) unsigned char dynbuf[];
    const float4* sbp[2] = { (const float4*)dynbuf,
                             (const float4*)(dynbuf + SLMAX * 16) };
    uint32_t sba[2];
    sba[0] = (uint32_t)__cvta_generic_to_shared(dynbuf);
    sba[1] = sba[0] + SLMAX * 16;

    __shared__ float sM[64 * 6];
    __shared__ float sZ[64];
    __shared__ unsigned sred[24];
    __shared__ float ssum[8];
    __shared__ int s_u;

#define GRAB(ci) ({ __syncthreads(); \
    if (threadIdx.x == 0) s_u = (int)atomicAdd(&g_ctr[ci], 1u); \
    __syncthreads(); s_u; })

    // ---- P1: minmax, cp.async double-buffered work stealing (4608 units) ----
    {
        int cur = GRAB(0);
        if (cur < 4608) p12_issue(cur, sba[0], l1, l2, l3, l4, l5);
        cp_commit();
        int nxt = (cur < 4608) ? GRAB(0) : 4608;
        if (nxt < 4608) p12_issue(nxt, sba[1], l1, l2, l3, l4, l5);
        cp_commit();
        int pb = 0;
        while (cur < 4608) {
            cp_wait<1>();
            p1_process(cur, sbp[pb]);
            cur = nxt; pb ^= 1;
            nxt = (cur < 4608) ? GRAB(0) : 4608;
            if (nxt < 4608) p12_issue(nxt, sba[pb ^ 1], l1, l2, l3, l4, l5);
            cp_commit();
        }
        cp_wait<0>();
    }
    // NO global barrier: P2 synchronizes per channel via g_arr1

    // ---- P2: hist + gidx (+ inline stats), ascending order ----
    {
        int cur = GRAB(1);
        if (cur < 4608) p12_issue(cur, sba[0], l1, l2, l3, l4, l5);
        cp_commit();
        int nxt = (cur < 4608) ? GRAB(1) : 4608;
        if (nxt < 4608) p12_issue(nxt, sba[1], l1, l2, l3, l4, l5);
        cp_commit();
        int pb = 0;
        while (cur < 4608) {
            cp_wait<1>();
            p2_process(cur, sbp[pb]);
            cur = nxt; pb ^= 1;
            nxt = (cur < 4608) ? GRAB(1) : 4608;
            if (nxt < 4608) p12_issue(nxt, sba[pb ^ 1], l1, l2, l3, l4, l5);
            cp_commit();
        }
        cp_wait<0>();
    }
    gridbar(1 * NB);

    // ---- P4: proc sums, work-stolen (439 uniform units) ----
    {
        int u = GRAB(2);
        while (u < 439) {
            if (u < 225)       proc_unit<64, 480, 480, true>(0u, 0, 0, u, 0, sM, sZ);
            else if (u < 339) { int i = u - 225;
                                proc_unit<128, 240, 240, false>(14745600u, 230400, 64, i >> 1, i & 1, sM, sZ); }
            else if (u < 399) { int i = u - 339;
                                proc_unit<256, 120, 120, false>(22118400u, 288000, 192, i >> 2, i & 3, sM, sZ); }
            else if (u < 431) { int i = u - 399;
                                proc_unit<512, 60, 60, false>(25804800u, 302400, 448, i >> 3, i & 7, sM, sZ); }
            else              { int i = u - 431;
                                proc_unit<512, 30, 30, false>(27648000u, 306000, 960, 0, i, sM, sZ); }
            u = GRAB(2);
        }
    }
    gridbar(2 * NB);

    // ---- P5: all-layer pmin/pmax (76725 float4, 1/thread) ----
    {
        if (threadIdx.x < 5) { sred[threadIdx.x] = 0xffffffffu; sred[12 + threadIdx.x] = 0u; }
        __syncthreads();
        int tg = blockIdx.x * 256 + threadIdx.x;
        if (tg < 76725) {
            float4 v = ((const float4*)g_proc)[tg];
            int l = (tg < 57600) ? 0 : (tg < 72000) ? 1 : (tg < 75600) ? 2
                  : (tg < 76500) ? 3 : 4;
            float mn = fminf(fminf(v.x, v.y), fminf(v.z, v.w));
            float mx = fmaxf(fmaxf(v.x, v.y), fmaxf(v.z, v.w));
            atomicMin(&sred[l], fenc(mn));
            atomicMax(&sred[12 + l], fenc(mx));
        }
        __syncthreads();
        if (threadIdx.x < 5) {
            atomicMin(&g_pmin[threadIdx.x], sred[threadIdx.x]);
            atomicMax(&g_pmax[threadIdx.x], sred[12 + threadIdx.x]);
        }
    }
    gridbar(3 * NB);

    // ---- P6: resize, work-stolen (1125 units) ----
    {
        int u = GRAB(3);
        while (u < 1125) {
            if (u < 225)      resize_unit<480>(u, 0, 0, sred, ssum);
            else if (u < 450) resize_unit<240>(u - 225, 230400, 1, sred, ssum);
            else if (u < 675) resize_unit<120>(u - 450, 288000, 2, sred, ssum);
            else if (u < 900) resize_unit<60>(u - 675, 302400, 3, sred, ssum);
            else              resize_unit<30>(u - 900, 306000, 4, sred, ssum);
            u = GRAB(3);
        }
    }
    gridbar(4 * NB);

    // ---- P7: final groups + sum ----
    if (blockIdx.x < 225) {
        int idx = blockIdx.x * 256 + threadIdx.x;
        float s = 0.f;
#pragma unroll
        for (int l = 0; l < 5; l++) {
            float v = g_resized[l * 57600 + idx];
            float rmn = fdec(g_rmin[l]);
            float rmx = fdec(g_rmax[l]);
            float rrng = rmx - rmn;
            float rmean = g_rsum[l] / 57600.f;
            float t = rmx - rmean;
            float w3 = t * t;
            float g = (rrng == 0.f || w3 == 0.f)
                      ? 0.f
                      : __fmul_rn(__fdiv_rn(__fsub_rn(v, rmn), rrng), 256.f);
            s += g;
            out[57600 + idx * 5 + l] = g;
        }
        out[idx] = s;
    }
#undef GRAB
}

extern "C" void kernel_launch(void* const* d_in, const int* in_sizes, int n_in,
                              void* d_out, int out_size) {
    const float* l1 = (const float*)d_in[0];
    const float* l2 = (const float*)d_in[1];
    const float* l3 = (const float*)d_in[2];
    const float* l4 = (const float*)d_in[3];
    const float* l5 = (const float*)d_in[4];
    float* out = (float*)d_out;

    cudaFuncSetAttribute(k_main, cudaFuncAttributeMaxDynamicSharedMemorySize,
                         DYNSMEM);
    k_init<<<300, 256>>>();
    k_main<<<NB, 256, DYNSMEM>>>(l1, l2, l3, l4, l5, out);
}

// round 16
// speedup vs baseline: 1.2311x; 1.1561x over previous
#include <cuda_runtime.h>
#include <cuda_bf16.h>
#include <math.h>
#include <float.h>
#include <stdint.h>

// ---------------------------------------------------------------------------
// DeepRare. Two persistent kernels split at the P3/P4 boundary:
//  k_front (NB=444, 57.6KB smem): P1 minmax + P2 hist/gidx (R11 champion
//    structure verbatim) + P3 stats spread wide.
//  k_tail (740 blocks, ~2KB smem, 6 blocks/SM): P4 proc, P5 pminmax,
//    P6 resize (layer-2 = identity), P7 final -- at 2x the occupancy.
// ---------------------------------------------------------------------------

#define NCH 1472
#define GIDX_TOTAL 28108800
#define NB 444            // k_front: 148 SMs x 3 blocks single wave
#define NB2 740           // k_tail: 148 SMs x 5 (cap 6/SM) single wave
#define SLMAX 1800        // unit size in float4 (28.8 KB)
#define DYNSMEM (2 * SLMAX * 16)

__device__ unsigned g_bar, g_bar2;
__device__ unsigned g_ctr[4];
__device__ unsigned g_cmin[NCH], g_cmax[NCH];
__device__ unsigned g_hist[NCH][6], g_hist2[NCH][6];
__device__ float g_M[NCH][6], g_Z[NCH];
__device__ __align__(16) unsigned char g_gidx[GIDX_TOTAL];
__device__ __align__(16) float g_proc[306912];
__device__ unsigned g_pmin[5], g_pmax[5];
__device__ float g_resized[5 * 57600];
__device__ unsigned g_rmin[5], g_rmax[5];
__device__ float g_rsum[5];

__device__ __forceinline__ unsigned fenc(float f) {
    unsigned u = __float_as_uint(f);
    return (u & 0x80000000u) ? ~u : (u | 0x80000000u);
}
__device__ __forceinline__ float fdec(unsigned e) {
    return (e & 0x80000000u) ? __uint_as_float(e & 0x7fffffffu)
                             : __uint_as_float(~e);
}

__device__ __forceinline__ void gbar(unsigned* ctr, unsigned tgt) {
    __syncthreads();
    if (threadIdx.x == 0) {
        __threadfence();
        atomicAdd(ctr, 1u);
        volatile unsigned* p = ctr;
        while (*p < tgt) { __nanosleep(20); }
        __threadfence();
    }
    __syncthreads();
}

// ---- cp.async primitives ---------------------------------------------------
__device__ __forceinline__ void cp16(uint32_t dst, const void* src) {
    asm volatile("cp.async.cg.shared.global [%0], [%1], 16;\n"
                 :: "r"(dst), "l"(src));
}
__device__ __forceinline__ void cp_commit() {
    asm volatile("cp.async.commit_group;\n");
}
template <int N>
__device__ __forceinline__ void cp_wait() {
    asm volatile("cp.async.wait_group %0;\n" :: "n"(N));
}

__global__ void k_init() {
    int i = blockIdx.x * 256 + threadIdx.x;
    if (i == 0) { g_bar = 0u; g_bar2 = 0u; }
    if (i < 4) g_ctr[i] = 0u;
    if (i < NCH * 6) {
        ((unsigned*)g_hist)[i] = 0u;
        ((unsigned*)g_hist2)[i] = 0u;
    }
    if (i < NCH) { g_cmin[i] = 0xffffffffu; g_cmax[i] = 0u; }
    if (i < 76512) g_proc[230400 + i] = 0.f;   // l2..l5 (atomic-accumulated)
    if (i < 5) {
        g_pmin[i] = 0xffffffffu; g_pmax[i] = 0u;
        g_rmin[i] = 0xffffffffu; g_rmax[i] = 0u;
        g_rsum[i] = 0.f;
    }
}

// ---- masked float4 (borders -> 0) -------------------------------------------
template <int H, int W>
__device__ __forceinline__ void mask4(int fc, float4 v,
                                      float& v0, float& v1, float& v2, float& v3) {
    if constexpr (W % 4 == 0) {
        constexpr int W4 = W / 4;
        int row = fc / W4;
        int col = fc - row * W4;
        bool br = (row == 0) | (row == H - 1);
        v0 = (br | (col == 0))      ? 0.f : v.x;
        v1 = br                      ? 0.f : v.y;
        v2 = br                      ? 0.f : v.z;
        v3 = (br | (col == W4 - 1)) ? 0.f : v.w;
    } else {
        int e = fc * 4;
        int y0 = e / W, x0 = e - y0 * W;
        int y1 = (e+1) / W, x1 = (e+1) - y1 * W;
        int y2 = (e+2) / W, x2 = (e+2) - y2 * W;
        int y3 = (e+3) / W, x3 = (e+3) - y3 * W;
        v0 = ((y0==0)|(x0==0)|(y0==H-1)|(x0==W-1)) ? 0.f : v.x;
        v1 = ((y1==0)|(x1==0)|(y1==H-1)|(x1==W-1)) ? 0.f : v.y;
        v2 = ((y2==0)|(x2==0)|(y2==H-1)|(x2==W-1)) ? 0.f : v.z;
        v3 = ((y3==0)|(x3==0)|(y3==H-1)|(x3==W-1)) ? 0.f : v.w;
    }
}

// ---- unit geometry (4608 units) ----------------------------------------------
template <int SL, int CHF4>
__device__ __forceinline__ void issue_unit(const float* __restrict__ in,
                                           int c, int s, uint32_t sbuf) {
    const float4* p4 = (const float4*)in + (size_t)c * CHF4 + (size_t)s * SL;
    constexpr int K = (SL + 255) / 256;
#pragma unroll
    for (int k = 0; k < K; k++) {
        int fl = k * 256 + threadIdx.x;
        if (SL % 256 == 0 || fl < SL) cp16(sbuf + fl * 16, p4 + fl);
    }
}

__device__ __forceinline__ void p12_issue(int u, uint32_t sbuf,
    const float* __restrict__ l1, const float* __restrict__ l2,
    const float* __restrict__ l3, const float* __restrict__ l4,
    const float* __restrict__ l5) {
    if (u < 2048)      issue_unit<1800, 57600>(l1, u >> 5, u & 31, sbuf);
    else if (u < 3072) issue_unit<1800, 14400>(l2, (u - 2048) >> 3, (u - 2048) & 7, sbuf);
    else if (u < 3584) issue_unit<1800, 3600>(l3, (u - 3072) >> 1, (u - 3072) & 1, sbuf);
    else if (u < 4096) issue_unit<900, 900>(l4, u - 3584, 0, sbuf);
    else               issue_unit<225, 225>(l5, u - 4096, 0, sbuf);
}

// -------- P1 process: min/max from smem chunk ----------------------------------
template <int H, int W, int SL>
__device__ __forceinline__ void mm_process(const float4* __restrict__ sbuf,
                                           int choff, int c, int s) {
    const int fbase = s * SL;
    constexpr int K = (SL + 255) / 256;
    float mn = 0.f, mx = 0.f;   // 0 always present in channel (borders)
#pragma unroll
    for (int k = 0; k < K; k++) {
        int fl = k * 256 + threadIdx.x;
        if (SL % 256 == 0 || fl < SL) {
            float4 v = sbuf[fl];
            float v0, v1, v2, v3;
            mask4<H, W>(fbase + fl, v, v0, v1, v2, v3);
            mn = fminf(mn, fminf(fminf(v0, v1), fminf(v2, v3)));
            mx = fmaxf(mx, fmaxf(fmaxf(v0, v1), fmaxf(v2, v3)));
        }
    }
    unsigned emn = __reduce_min_sync(0xffffffffu, fenc(mn));
    unsigned emx = __reduce_max_sync(0xffffffffu, fenc(mx));
    if ((threadIdx.x & 31) == 0) {
        atomicMin(&g_cmin[choff + c], emn);
        atomicMax(&g_cmax[choff + c], emx);
    }
}

__device__ __forceinline__ void p1_process(int u, const float4* sbuf) {
    if (u < 2048)      mm_process<480, 480, 1800>(sbuf, 0, u >> 5, u & 31);
    else if (u < 3072) mm_process<240, 240, 1800>(sbuf, 64, (u - 2048) >> 3, (u - 2048) & 7);
    else if (u < 3584) mm_process<120, 120, 1800>(sbuf, 192, (u - 3072) >> 1, (u - 3072) & 1);
    else if (u < 4096) mm_process<60, 60, 900>(sbuf, 448, u - 3584, 0);
    else               mm_process<30, 30, 225>(sbuf, 960, u - 4096, 0);
}

// -------- P2 process: dual 6-bin hist + gidx from smem chunk --------------------
template <int H, int W, int SL, int CHF4>
__device__ __forceinline__ void hist_process(const float4* __restrict__ sbuf,
                                             int choff, size_t gidxoff,
                                             int c, int s) {
    const int gc = choff + c;
    uchar4* go = (uchar4*)(g_gidx + gidxoff) + (size_t)c * CHF4 + (size_t)s * SL;
    const int fbase = s * SL;
    constexpr int K = (SL + 255) / 256;
    const float mn = fdec(g_cmin[gc]);
    const float mx = fdec(g_cmax[gc]);
    const float rng = mx - mn;
    float inv6, mn6;
    if (rng == 0.f) { inv6 = 0.f; mn6 = 0.f; }
    else { inv6 = __fdiv_rn(1536.f, rng); mn6 = __fmul_rn(-mn, inv6); }
    unsigned pk1 = 0u, pk2 = 0u, nact = 0u;
#pragma unroll
    for (int k = 0; k < K; k++) {
        int fl = k * 256 + threadIdx.x;
        if (SL % 256 == 0 || fl < SL) {
            float4 v = sbuf[fl];
            float vv[4];
            mask4<H, W>(fbase + fl, v, vv[0], vv[1], vv[2], vv[3]);
            unsigned gb[4];
#pragma unroll
            for (int kk = 0; kk < 4; kk++) {
                float u6 = __fmaf_rn(vv[kk], inv6, mn6);
                int iu = (int)floorf(u6);
                int bin = min(5, max(0, iu >> 8));
                int g = min(5, max(0, iu - 1));
                pk1 += 1u << (bin * 6);
                pk2 += 1u << (g * 6);
                gb[kk] = (unsigned)g;
            }
            nact += 4u;
            go[fl] = make_uchar4(gb[0], gb[1], gb[2], gb[3]);
        }
    }
    unsigned f1[6], f2[6], s1 = 0u, s2 = 0u;
#pragma unroll
    for (int b = 0; b < 5; b++) {
        f1[b] = (pk1 >> (b * 6)) & 63u; s1 += f1[b];
        f2[b] = (pk2 >> (b * 6)) & 63u; s2 += f2[b];
    }
    f1[5] = nact - s1; f2[5] = nact - s2;
#pragma unroll
    for (int b = 0; b < 6; b++) {
        f1[b] = __reduce_add_sync(0xffffffffu, f1[b]);
        f2[b] = __reduce_add_sync(0xffffffffu, f2[b]);
    }
    if ((threadIdx.x & 31) == 0) {
#pragma unroll
        for (int b = 0; b < 6; b++) {
            if (f1[b]) atomicAdd(&g_hist[gc][b], f1[b]);
            if (f2[b]) atomicAdd(&g_hist2[gc][b], f2[b]);
        }
    }
}

__device__ __forceinline__ void p2_process(int u, const float4* sbuf) {
    if (u < 2048)      hist_process<480, 480, 1800, 57600>(sbuf, 0, 0u, u >> 5, u & 31);
    else if (u < 3072) hist_process<240, 240, 1800, 14400>(sbuf, 64, 14745600u, (u - 2048) >> 3, (u - 2048) & 7);
    else if (u < 3584) hist_process<120, 120, 1800, 3600>(sbuf, 192, 22118400u, (u - 3072) >> 1, (u - 3072) & 1);
    else if (u < 4096) hist_process<60, 60, 900, 900>(sbuf, 448, 25804800u, u - 3584, 0);
    else               hist_process<30, 30, 225, 225>(sbuf, 960, 27648000u, u - 4096, 0);
}

// -------- P3: closed-form per-channel tables ------------------------------------
__device__ void stats_ch(int gc) {
    int choff, H, W;
    if (gc < 64)       { choff = 0;   H = 480; W = 480; }
    else if (gc < 192) { choff = 64;  H = 240; W = 240; }
    else if (gc < 448) { choff = 192; H = 120; W = 120; }
    else if (gc < 960) { choff = 448; H = 60;  W = 60;  }
    else               { choff = 960; H = 30;  W = 30;  }
    const int c = gc - choff;
    const float Nf = (float)(H * W);
    const int Nb = 2 * (H + W) - 4;

    float mn = fdec(g_cmin[gc]), mx = fdec(g_cmax[gc]);
    float rng = mx - mn;

    float hl[6]; unsigned h2[6];
#pragma unroll
    for (int b = 0; b < 6; b++) {
        float pr = __fadd_rn(__fdiv_rn((float)g_hist[gc][b], Nf), 1e-4f);
        hl[b] = -logf(pr);
        h2[b] = g_hist2[gc][b];
    }
    float dmin = FLT_MAX, dmax = -FLT_MAX, s = 0.f;
#pragma unroll
    for (int b = 0; b < 6; b++) if (h2[b]) {
        dmin = fminf(dmin, hl[b]); dmax = fmaxf(dmax, hl[b]);
        s += (float)h2[b] * hl[b];
    }
    float drng = dmax - dmin;
    float L[6];
    if (drng == 0.f) {
#pragma unroll
        for (int b = 0; b < 6; b++) L[b] = 0.f;
    } else {
        float meann = (s / Nf - dmin) / drng;
        float t = 1.f - meann;
        float w1 = t * t;
#pragma unroll
        for (int b = 0; b < 6; b++) L[b] = (hl[b] - dmin) / drng * w1;
    }
    // border gidx: EXACTLY the P2 formula applied to v=0 (u6 = mn6)
    int gb = 0;
    if (rng != 0.f) {
        float inv6 = __fdiv_rn(1536.f, rng);
        float mn6 = __fmul_rn(-mn, inv6);
        int iu = (int)floorf(mn6);
        gb = min(5, max(0, iu - 1));
    }
    float mmin = FLT_MAX, mmax = -FLT_MAX, s2 = 0.f;
#pragma unroll
    for (int b = 0; b < 6; b++) {
        unsigned cnt = h2[b];
        if (c > 0 && b == gb) cnt -= (unsigned)Nb;
        if (cnt) {
            mmin = fminf(mmin, L[b]); mmax = fmaxf(mmax, L[b]);
            s2 += (float)cnt * L[b];
        }
    }
    if (c > 0) { mmin = fminf(mmin, 0.f); mmax = fmaxf(mmax, 0.f); }
    float mrng = mmax - mmin;
    if (mrng == 0.f) {
#pragma unroll
        for (int b = 0; b < 6; b++) g_M[gc][b] = 0.f;
        g_Z[gc] = 0.f;
    } else {
        float mmean = s2 / Nf;
        float t = mmax - mmean;
        float w2 = t * t;
#pragma unroll
        for (int b = 0; b < 6; b++) g_M[gc][b] = (L[b] - mmin) / mrng * w2;
        g_Z[gc] = (0.f - mmin) / mrng * w2;
    }
}

// ---------------------------- k_front: P1 + P2 + P3 ------------------------------
__global__ __launch_bounds__(256, 3) void k_front(
    const float* __restrict__ l1, const float* __restrict__ l2,
    const float* __restrict__ l3, const float* __restrict__ l4,
    const float* __restrict__ l5) {
    extern __shared__ __align__(16) unsigned char dynbuf[];
    const float4* sbp[2] = { (const float4*)dynbuf,
                             (const float4*)(dynbuf + SLMAX * 16) };
    uint32_t sba[2];
    sba[0] = (uint32_t)__cvta_generic_to_shared(dynbuf);
    sba[1] = sba[0] + SLMAX * 16;
    __shared__ int s_u;

#define GRAB(ci) ({ __syncthreads(); \
    if (threadIdx.x == 0) s_u = (int)atomicAdd(&g_ctr[ci], 1u); \
    __syncthreads(); s_u; })

    // ---- P1: minmax, cp.async double-buffered work stealing (4608 units) ----
    {
        int cur = GRAB(0);
        if (cur < 4608) p12_issue(cur, sba[0], l1, l2, l3, l4, l5);
        cp_commit();
        int nxt = (cur < 4608) ? GRAB(0) : 4608;
        if (nxt < 4608) p12_issue(nxt, sba[1], l1, l2, l3, l4, l5);
        cp_commit();
        int pb = 0;
        while (cur < 4608) {
            cp_wait<1>();
            p1_process(cur, sbp[pb]);
            cur = nxt; pb ^= 1;
            nxt = (cur < 4608) ? GRAB(0) : 4608;
            if (nxt < 4608) p12_issue(nxt, sba[pb ^ 1], l1, l2, l3, l4, l5);
            cp_commit();
        }
        cp_wait<0>();
    }
    gbar(&g_bar, 1 * NB);

    // ---- P2: hist + gidx, reversed order (recent layers L2-hot) ----
    {
        int ur = GRAB(1);
        int cur = (ur < 4608) ? (4607 - ur) : -1;
        if (cur >= 0) p12_issue(cur, sba[0], l1, l2, l3, l4, l5);
        cp_commit();
        int ur2 = (cur >= 0) ? GRAB(1) : 4608;
        int nxt = (ur2 < 4608) ? (4607 - ur2) : -1;
        if (nxt >= 0) p12_issue(nxt, sba[1], l1, l2, l3, l4, l5);
        cp_commit();
        int pb = 0;
        while (cur >= 0) {
            cp_wait<1>();
            p2_process(cur, sbp[pb]);
            cur = nxt; pb ^= 1;
            if (cur >= 0) {
                int ur3 = GRAB(1);
                nxt = (ur3 < 4608) ? (4607 - ur3) : -1;
                if (nxt >= 0) p12_issue(nxt, sba[pb ^ 1], l1, l2, l3, l4, l5);
            }
            cp_commit();
        }
        cp_wait<0>();
    }
    gbar(&g_bar, 2 * NB);

    // ---- P3: per-channel tables, spread wide (blocks 0-5, 1472 threads) ----
    {
        int gc = blockIdx.x * 256 + threadIdx.x;
        if (gc < NCH) stats_ch(gc);
    }
#undef GRAB
}

// -------- P4 unit: proc += sum of 64 channels of M[c][gidx] ----------------------
template <int C, int H, int W, bool DIRECT>
__device__ __forceinline__ void proc_unit(size_t gidxoff, int procoff,
                                          int choff, int pxblk, int cslice,
                                          float* sM, float* sZ) {
    constexpr int CS = 64;
    constexpr int HW = H * W;
    constexpr int NQ = HW / 4;
    const int cbeg = cslice * CS;
    for (int i = threadIdx.x; i < CS * 6; i += 256)
        sM[i] = ((const float*)g_M)[(choff + cbeg) * 6 + i];
    if (threadIdx.x < CS) sZ[threadIdx.x] = g_Z[choff + cbeg + threadIdx.x];
    __syncthreads();

    int q = pxblk * 256 + threadIdx.x;
    bool act = q < NQ;
    bool bf0 = false, bf1 = false, bf2 = false, bf3 = false;
    if (act) {
        if constexpr (W % 4 == 0) {
            constexpr int W4 = W / 4;
            int row = q / W4, col = q - row * W4;
            bool br = (row == 0) | (row == H - 1);
            bf0 = br | (col == 0); bf1 = br; bf2 = br;
            bf3 = br | (col == W4 - 1);
        } else {
            int e = q * 4;
#pragma unroll
            for (int k = 0; k < 4; k++) {
                int y = (e + k) / W, x = (e + k) - y * W;
                bool bb = (y == 0) | (x == 0) | (y == H - 1) | (x == W - 1);
                if (k == 0) bf0 = bb; else if (k == 1) bf1 = bb;
                else if (k == 2) bf2 = bb; else bf3 = bb;
            }
        }
    }
    bool anyb = __any_sync(0xffffffffu, act && (bf0 | bf1 | bf2 | bf3));
    float a0 = 0.f, a1 = 0.f, a2 = 0.f, a3 = 0.f;
    if (act) {
        const uchar4* gp = (const uchar4*)(g_gidx + gidxoff) + q;
        if (!anyb) {
#pragma unroll 8
            for (int cc = 0; cc < CS; cc++) {
                uchar4 gv = gp[(size_t)(cbeg + cc) * NQ];
                const float* mc = sM + cc * 6;
                a0 += mc[gv.x]; a1 += mc[gv.y]; a2 += mc[gv.z]; a3 += mc[gv.w];
            }
        } else {
#pragma unroll 8
            for (int cc = 0; cc < CS; cc++) {
                uchar4 gv = gp[(size_t)(cbeg + cc) * NQ];
                const float* mc = sM + cc * 6;
                bool ch0 = (cbeg + cc) == 0;   // layer ch 0 keeps border
                float z = sZ[cc];
                a0 += (bf0 && !ch0) ? z : mc[gv.x];
                a1 += (bf1 && !ch0) ? z : mc[gv.y];
                a2 += (bf2 && !ch0) ? z : mc[gv.z];
                a3 += (bf3 && !ch0) ? z : mc[gv.w];
            }
        }
        if constexpr (DIRECT) {
            ((float4*)(g_proc + procoff))[q] = make_float4(a0, a1, a2, a3);
        } else {
            float* pp = g_proc + procoff + q * 4;
            atomicAdd(pp + 0, a0); atomicAdd(pp + 1, a1);
            atomicAdd(pp + 2, a2); atomicAdd(pp + 3, a3);
        }
    }
}

// -------- P6 unit: resize + fused normalize/threshold + r-stats ------------------
template <int S>
__device__ __forceinline__ void resize_unit(int b, int procoff, int layer,
                                            unsigned* sred, float* ssum) {
    int idx = b * 256 + threadIdx.x;   // 57600 = 225*256 exact
    float pmn = fdec(g_pmin[layer]);
    float pmx = fdec(g_pmax[layer]);
    float prng = pmx - pmn;
    float acc;
    if constexpr (S == 240) {
        // identity: triangle weights are exactly {0,1,0} at scale 1
        float v = g_proc[procoff + idx];
        float n = (prng == 0.f) ? 0.f : __fdiv_rn(__fsub_rn(v, pmn), prng);
        acc = (n < 0.2f) ? 0.f : n;
    } else {
        int oy = idx / 240, ox = idx - oy * 240;
        constexpr float inv = (float)S / 240.f;
        constexpr float ks = (S > 240) ? inv : 1.f;
        constexpr float iks = 1.f / ks;
        float fy = (oy + 0.5f) * inv - 0.5f;
        float fx = (ox + 0.5f) * inv - 0.5f;
        int y0 = max(0, (int)ceilf(fy - ks)), y1 = min(S - 1, (int)floorf(fy + ks));
        int x0 = max(0, (int)ceilf(fx - ks)), x1 = min(S - 1, (int)floorf(fx + ks));
        float wy[4], wx[4];
        float sy = 0.f, sx = 0.f;
#pragma unroll
        for (int j = 0; j < 4; j++) {
            int yy = y0 + j;
            float w = (yy <= y1) ? fmaxf(0.f, 1.f - fabsf(fy - (float)yy) * iks) : 0.f;
            wy[j] = w; sy += w;
            int xx = x0 + j;
            float v = (xx <= x1) ? fmaxf(0.f, 1.f - fabsf(fx - (float)xx) * iks) : 0.f;
            wx[j] = v; sx += v;
        }
#pragma unroll
        for (int j = 0; j < 4; j++) {
            wy[j] = __fdiv_rn(wy[j], sy);
            wx[j] = __fdiv_rn(wx[j], sx);
        }
        const float* p = g_proc + procoff;
        acc = 0.f;
#pragma unroll
        for (int jy = 0; jy < 4; jy++) {
            if (y0 + jy > y1) break;
            const float* row = p + (y0 + jy) * S;
            float r = 0.f;
#pragma unroll
            for (int jx = 0; jx < 4; jx++) {
                if (x0 + jx > x1) break;
                float v = row[x0 + jx];
                float n = (prng == 0.f) ? 0.f : __fdiv_rn(__fsub_rn(v, pmn), prng);
                n = (n < 0.2f) ? 0.f : n;
                r += wx[jx] * n;
            }
            acc += wy[jy] * r;
        }
    }
    g_resized[layer * 57600 + idx] = acc;

    unsigned* smn = sred; unsigned* smx = sred + 8;
    unsigned emn = __reduce_min_sync(0xffffffffu, fenc(acc));
    unsigned emx = __reduce_max_sync(0xffffffffu, fenc(acc));
    float wsum = acc;
#pragma unroll
    for (int o = 16; o; o >>= 1) wsum += __shfl_xor_sync(0xffffffffu, wsum, o);
    if ((threadIdx.x & 31) == 0) {
        int w = threadIdx.x >> 5;
        smn[w] = emn; smx[w] = emx; ssum[w] = wsum;
    }
    __syncthreads();
    if (threadIdx.x == 0) {
        unsigned a = smn[0], bb = smx[0]; float s = ssum[0];
#pragma unroll
        for (int w = 1; w < 8; w++) {
            a = min(a, smn[w]); bb = max(bb, smx[w]); s += ssum[w];
        }
        atomicMin(&g_rmin[layer], a);
        atomicMax(&g_rmax[layer], bb);
        atomicAdd(&g_rsum[layer], s);
    }
    __syncthreads();
}

__device__ __forceinline__ void p6_dispatch(int u, unsigned* sred, float* ssum) {
    if (u < 225)      resize_unit<480>(u, 0, 0, sred, ssum);
    else if (u < 450) resize_unit<240>(u - 225, 230400, 1, sred, ssum);
    else if (u < 675) resize_unit<120>(u - 450, 288000, 2, sred, ssum);
    else if (u < 900) resize_unit<60>(u - 675, 302400, 3, sred, ssum);
    else              resize_unit<30>(u - 900, 306000, 4, sred, ssum);
}

// ---------------------------- k_tail: P4..P7 (high occupancy) --------------------
__global__ __launch_bounds__(256, 6) void k_tail(float* __restrict__ out) {
    __shared__ float sM[64 * 6];
    __shared__ float sZ[64];
    __shared__ unsigned sred[24];
    __shared__ float ssum[8];
    const int blk = blockIdx.x;

    // ---- P4: proc sums (439 static uniform units) ----
    if (blk < 439) {
        int u = blk;
        if (u < 225)       proc_unit<64, 480, 480, true>(0u, 0, 0, u, 0, sM, sZ);
        else if (u < 339) { int i = u - 225;
                            proc_unit<128, 240, 240, false>(14745600u, 230400, 64, i >> 1, i & 1, sM, sZ); }
        else if (u < 399) { int i = u - 339;
                            proc_unit<256, 120, 120, false>(22118400u, 288000, 192, i >> 2, i & 3, sM, sZ); }
        else if (u < 431) { int i = u - 399;
                            proc_unit<512, 60, 60, false>(25804800u, 302400, 448, i >> 3, i & 7, sM, sZ); }
        else              { int i = u - 431;
                            proc_unit<512, 30, 30, false>(27648000u, 306000, 960, 0, i, sM, sZ); }
    }
    gbar(&g_bar2, 1 * NB2);

    // ---- P5: all-layer pmin/pmax (76725 float4, 1/thread) ----
    {
        if (threadIdx.x < 5) { sred[threadIdx.x] = 0xffffffffu; sred[12 + threadIdx.x] = 0u; }
        __syncthreads();
        int tg = blk * 256 + threadIdx.x;
        if (tg < 76725) {
            float4 v = ((const float4*)g_proc)[tg];
            int l = (tg < 57600) ? 0 : (tg < 72000) ? 1 : (tg < 75600) ? 2
                  : (tg < 76500) ? 3 : 4;
            float mn = fminf(fminf(v.x, v.y), fminf(v.z, v.w));
            float mx = fmaxf(fmaxf(v.x, v.y), fmaxf(v.z, v.w));
            atomicMin(&sred[l], fenc(mn));
            atomicMax(&sred[12 + l], fenc(mx));
        }
        __syncthreads();
        if (threadIdx.x < 5) {
            atomicMin(&g_pmin[threadIdx.x], sred[threadIdx.x]);
            atomicMax(&g_pmax[threadIdx.x], sred[12 + threadIdx.x]);
        }
    }
    gbar(&g_bar2, 2 * NB2);

    // ---- P6: resize (1125 static units, 2 rounds) ----
    p6_dispatch(blk, sred, ssum);
    if (blk + NB2 < 1125) p6_dispatch(blk + NB2, sred, ssum);
    gbar(&g_bar2, 3 * NB2);

    // ---- P7: final groups + sum ----
    if (blk < 225) {
        int idx = blk * 256 + threadIdx.x;
        float s = 0.f;
#pragma unroll
        for (int l = 0; l < 5; l++) {
            float v = g_resized[l * 57600 + idx];
            float rmn = fdec(g_rmin[l]);
            float rmx = fdec(g_rmax[l]);
            float rrng = rmx - rmn;
            float rmean = g_rsum[l] / 57600.f;
            float t = rmx - rmean;
            float w3 = t * t;
            float g = (rrng == 0.f || w3 == 0.f)
                      ? 0.f
                      : __fmul_rn(__fdiv_rn(__fsub_rn(v, rmn), rrng), 256.f);
            s += g;
            out[57600 + idx * 5 + l] = g;
        }
        out[idx] = s;
    }
}

extern "C" void kernel_launch(void* const* d_in, const int* in_sizes, int n_in,
                              void* d_out, int out_size) {
    const float* l1 = (const float*)d_in[0];
    const float* l2 = (const float*)d_in[1];
    const float* l3 = (const float*)d_in[2];
    const float* l4 = (const float*)d_in[3];
    const float* l5 = (const float*)d_in[4];
    float* out = (float*)d_out;

    cudaFuncSetAttribute(k_front, cudaFuncAttributeMaxDynamicSharedMemorySize,
                         DYNSMEM);
    k_init<<<300, 256>>>();
    k_front<<<NB, 256, DYNSMEM>>>(l1, l2, l3, l4, l5);
    k_tail<<<NB2, 256>>>(out);
}